// round 16
// baseline (speedup 1.0000x reference)
#include <cuda_runtime.h>
#include <cuda_bf16.h>
#include <cstdint>

#define N_IN       16
#define FANIN      16
#define N_NODES    512
#define N_OUT      64
#define BATCH      32768
#define HALF       (BATCH / 2)          // 16384 packed pairs
#define OUT_START  (N_NODES - N_OUT)    // node 448

#define THREADS    256
#define GRID       (HALF / THREADS)     // 64 CTAs, 8 warps/SM = 2 warps/SMSP

#define PAD_NODES  (N_NODES + 2)        // rows 512,513 zero (lookahead tail)

using u32 = unsigned int;
using u64 = unsigned long long;

__constant__ float cB[PAD_NODES] = {};  // bias (zero-padded)
__constant__ float cR[N_OUT]     = {};  // response of output nodes

__device__ __forceinline__ float tanh_approx(float x) {
    float y; asm("tanh.approx.f32 %0, %1;" : "=f"(y) : "f"(x)); return y;
}
__device__ __forceinline__ u32 smem_u32(const void* p) {
    u32 a;
    asm("{ .reg .u64 t; cvta.to.shared.u64 t, %1; cvt.u32.u64 %0, t; }"
        : "=r"(a) : "l"(p));
    return a;
}
__device__ __forceinline__ void lds_v4(float4& d, u32 addr) {
    asm volatile("ld.shared.v4.f32 {%0,%1,%2,%3}, [%4];"
                 : "=f"(d.x), "=f"(d.y), "=f"(d.z), "=f"(d.w) : "r"(addr));
}
// ---- packed f32x2 helpers ----
__device__ __forceinline__ u64 pack2(float lo, float hi) {
    u64 r; asm("mov.b64 %0, {%1, %2};" : "=l"(r) : "f"(lo), "f"(hi)); return r;
}
__device__ __forceinline__ u64 dup2(float v) {            // {v, v} (ALU mov)
    u64 r; asm("mov.b64 %0, {%1, %1};" : "=l"(r) : "f"(v)); return r;
}
__device__ __forceinline__ void unpack2(u64 v, float& lo, float& hi) {
    asm("mov.b64 {%0, %1}, %2;" : "=f"(lo), "=f"(hi) : "l"(v));
}
__device__ __forceinline__ u64 fma2(u64 a, u64 b, u64 c) {
    u64 d; asm("fma.rn.f32x2 %0, %1, %2, %3;" : "=l"(d) : "l"(a), "l"(b), "l"(c)); return d;
}
__device__ __forceinline__ u64 mul2(u64 a, u64 b) {
    u64 d; asm("mul.rn.f32x2 %0, %1, %2;" : "=l"(d) : "l"(a), "l"(b)); return d;
}
__device__ __forceinline__ u64 add2(u64 a, u64 b) {
    u64 d; asm("add.rn.f32x2 %0, %1, %2;" : "=l"(d) : "l"(a), "l"(b)); return d;
}

__global__ void __launch_bounds__(THREADS, 1)
neat_forward_rp2x2w(const float* __restrict__ x,
                    const float* __restrict__ w,      // [512][16]
                    const float* __restrict__ resp,   // [512]
                    float*       __restrict__ out)    // [BATCH][64]
{
    __shared__ __align__(16) float sh_w[PAD_NODES * FANIN];   // ~32.9 KB

    const int tid = threadIdx.x;

    // Fold source responses into consumer weights:
    //   w'[i][t] = w[i][t] * resp[i + t - 16]  (identity for input sources).
    // Window carries RAW tanh values (packed pairs); resp applied at stores.
    for (int i = tid; i < N_NODES * FANIN; i += THREADS) {
        const int node = i >> 4, t = i & 15;
        const int g = node + t;
        const float s = (g >= N_IN) ? resp[g - N_IN] : 1.0f;
        sh_w[i] = w[i] * s;
    }
    for (int i = tid; i < 2 * FANIN; i += THREADS)
        sh_w[N_NODES * FANIN + i] = 0.0f;                      // pad rows
    __syncthreads();

    // One packed pair per thread: batch elements (b0, b0 + HALF).
    const int b0 = blockIdx.x * THREADS + tid;
    const int b1 = b0 + HALF;

    // Packed circular window: v2[g & 15] = {val_b0, val_b1} at global index g.
    u64 v2[16];
    {
        const float4* x0 = (const float4*)(x + (size_t)b0 * N_IN);
        const float4* x1 = (const float4*)(x + (size_t)b1 * N_IN);
        #pragma unroll
        for (int q = 0; q < 4; q++) {
            float4 t0 = x0[q], t1 = x1[q];
            v2[4*q+0] = pack2(t0.x, t1.x);
            v2[4*q+1] = pack2(t0.y, t1.y);
            v2[4*q+2] = pack2(t0.z, t1.z);
            v2[4*q+3] = pack2(t0.w, t1.w);
        }
    }

    float* outp0 = out + (size_t)b0 * N_OUT;
    float* outp1 = out + (size_t)b1 * N_OUT;
    const u32 wbase = smem_u32(sh_w);           // row stride 64 B

    // ---- Pipeline prologue ----
    u64 pp2, w15c2;
    {
        const float* r0 = sh_w;
        u64 a0 = fma2(v2[0], dup2(r0[0]), dup2(cB[0]));
        u64 a1 = mul2(v2[1], dup2(r0[1]));
        #pragma unroll
        for (int t = 2; t < 14; t += 2) {
            a0 = fma2(v2[t],     dup2(r0[t]),     a0);
            a1 = fma2(v2[t + 1], dup2(r0[t + 1]), a1);
        }
        a0 = fma2(v2[14], dup2(r0[14]), a0);
        pp2 = add2(a0, a1);
        w15c2 = dup2(r0[15]);
    }
    float4 cq0, cq1, cq2, cq3;                  // row of node 1
    {
        const float4* r1 = (const float4*)(sh_w + FANIN);
        cq0 = r1[0]; cq1 = r1[1]; cq2 = r1[2]; cq3 = r1[3];
    }

    float4 obA, obB;                            // output staging

    #pragma unroll 1
    for (int g = 0; g < N_NODES / 16; g++) {
        #pragma unroll
        for (int j = 0; j < 16; j++) {
            const int node = g * 16 + j;

            // ---- A: serial path (packed fma -> 2x tanh -> pack) ----
            const u64 yl2  = v2[(j + 15) & 15];         // y_{node-1} pair
            const u64 agg2 = fma2(yl2, w15c2, pp2);
            float aA, aB;
            unpack2(agg2, aA, aB);
            const float yA = tanh_approx(aA);
            const float yB = tanh_approx(aB);
            v2[j] = pack2(yA, yB);

            if (node >= OUT_START) {
                const int o = node - OUT_START;
                const float r = cR[o];
                const float oA = yA * r, oB = yB * r;
                if ((j & 3) == 0) { obA.x = oA; obB.x = oB; }
                if ((j & 3) == 1) { obA.y = oA; obB.y = oB; }
                if ((j & 3) == 2) { obA.z = oA; obB.z = oB; }
                if ((j & 3) == 3) {
                    obA.w = oA; obB.w = oB;
                    *(float4*)(outp0 + (o - 3)) = obA;
                    *(float4*)(outp1 + (o - 3)) = obB;
                }
            }

            // ---- B: prefetch weight row node+2 (volatile, used at j+1) ----
            float4 nq0, nq1, nq2, nq3;
            const u32 ra = wbase + (u32)(node + 2) * 64;
            lds_v4(nq0, ra);
            lds_v4(nq1, ra + 16);
            lds_v4(nq2, ra + 32);
            lds_v4(nq3, ra + 48);

            // ---- C: packed 15-tap partial for node+1, 4 split accumulators -
            // taps t=0..14 -> globals node+1 .. node+15 (slot j excluded).
            u64 a0 = fma2(v2[(j + 1)  & 15], dup2(cq0.x), dup2(cB[node + 1]));
            u64 a1 = mul2(v2[(j + 2)  & 15], dup2(cq0.y));
            u64 a2 = mul2(v2[(j + 3)  & 15], dup2(cq0.z));
            u64 a3 = mul2(v2[(j + 4)  & 15], dup2(cq0.w));
            a0 = fma2(v2[(j + 5)  & 15], dup2(cq1.x), a0);
            a1 = fma2(v2[(j + 6)  & 15], dup2(cq1.y), a1);
            a2 = fma2(v2[(j + 7)  & 15], dup2(cq1.z), a2);
            a3 = fma2(v2[(j + 8)  & 15], dup2(cq1.w), a3);
            a0 = fma2(v2[(j + 9)  & 15], dup2(cq2.x), a0);
            a1 = fma2(v2[(j + 10) & 15], dup2(cq2.y), a1);
            a2 = fma2(v2[(j + 11) & 15], dup2(cq2.z), a2);
            a3 = fma2(v2[(j + 12) & 15], dup2(cq2.w), a3);
            a0 = fma2(v2[(j + 13) & 15], dup2(cq3.x), a0);
            a1 = fma2(v2[(j + 14) & 15], dup2(cq3.y), a1);
            a2 = fma2(v2[(j + 15) & 15], dup2(cq3.z), a2);   // tap14 (newest) late
            pp2   = add2(add2(a0, a1), add2(a2, a3));
            w15c2 = dup2(cq3.w);

            // ---- rotate row pipeline ----
            cq0 = nq0; cq1 = nq1; cq2 = nq2; cq3 = nq3;
        }
    }
}

extern "C" void kernel_launch(void* const* d_in, const int* in_sizes, int n_in,
                              void* d_out, int out_size) {
    const float* x    = (const float*)d_in[0];   // [BATCH, 16]
    const float* w    = (const float*)d_in[1];   // [512, 16]
    const float* bias = (const float*)d_in[2];   // [512]
    const float* resp = (const float*)d_in[3];   // [512]
    // d_in[4] (src_idx) is the fixed sliding-window topology; baked into indexing.
    float* out = (float*)d_out;                  // [BATCH, 64]

    cudaMemcpyToSymbolAsync(cB, bias, N_NODES * sizeof(float), 0,
                            cudaMemcpyDeviceToDevice, 0);
    cudaMemcpyToSymbolAsync(cR, resp + OUT_START, N_OUT * sizeof(float), 0,
                            cudaMemcpyDeviceToDevice, 0);

    neat_forward_rp2x2w<<<GRID, THREADS>>>(x, w, resp, out);
}

// round 17
// speedup vs baseline: 1.3269x; 1.3269x over previous
#include <cuda_runtime.h>
#include <cuda_bf16.h>
#include <cstdint>

#define N_IN       16
#define FANIN      16
#define N_NODES    512
#define N_OUT      64
#define BATCH      32768
#define HALF       (BATCH / 2)          // 16384 packed pairs
#define OUT_START  (N_NODES - N_OUT)    // node 448

#define THREADS    128
#define GRID       (HALF / THREADS)     // 128 CTAs, 4 warps/SM = 1 warp/SMSP

#define PAD_NODES  (N_NODES + 2)        // rows 512,513 zero (lookahead tail)

using u32 = unsigned int;
using u64 = unsigned long long;

__constant__ float cB[PAD_NODES] = {};  // bias (zero-padded)
__constant__ float cR[N_OUT]     = {};  // response of output nodes

__device__ __forceinline__ float tanh_approx(float x) {
    float y; asm("tanh.approx.f32 %0, %1;" : "=f"(y) : "f"(x)); return y;
}
__device__ __forceinline__ u32 smem_u32(const void* p) {
    u32 a;
    asm("{ .reg .u64 t; cvta.to.shared.u64 t, %1; cvt.u32.u64 %0, t; }"
        : "=r"(a) : "l"(p));
    return a;
}
__device__ __forceinline__ void lds_v4(float4& d, u32 addr) {
    asm volatile("ld.shared.v4.f32 {%0,%1,%2,%3}, [%4];"
                 : "=f"(d.x), "=f"(d.y), "=f"(d.z), "=f"(d.w) : "r"(addr));
}
// ---- packed f32x2 helpers ----
__device__ __forceinline__ u64 pack2(float lo, float hi) {
    u64 r; asm("mov.b64 %0, {%1, %2};" : "=l"(r) : "f"(lo), "f"(hi)); return r;
}
// volatile: duplication is PINNED at the iteration tail (block D) so its
// results are >= 1 iteration old when consumed — no ALU->FMA exposure in C.
__device__ __forceinline__ u64 dup2v(float v) {
    u64 r; asm volatile("mov.b64 %0, {%1, %1};" : "=l"(r) : "f"(v)); return r;
}
__device__ __forceinline__ void unpack2(u64 v, float& lo, float& hi) {
    asm("mov.b64 {%0, %1}, %2;" : "=f"(lo), "=f"(hi) : "l"(v));
}
__device__ __forceinline__ u64 fma2(u64 a, u64 b, u64 c) {
    u64 d; asm("fma.rn.f32x2 %0, %1, %2, %3;" : "=l"(d) : "l"(a), "l"(b), "l"(c)); return d;
}
__device__ __forceinline__ u64 mul2(u64 a, u64 b) {
    u64 d; asm("mul.rn.f32x2 %0, %1, %2;" : "=l"(d) : "l"(a), "l"(b)); return d;
}
__device__ __forceinline__ u64 add2(u64 a, u64 b) {
    u64 d; asm("add.rn.f32x2 %0, %1, %2;" : "=l"(d) : "l"(a), "l"(b)); return d;
}

__global__ void __launch_bounds__(THREADS, 1)
neat_forward_rp3(const float* __restrict__ x,
                 const float* __restrict__ w,      // [512][16]
                 const float* __restrict__ resp,   // [512]
                 float*       __restrict__ out)    // [BATCH][64]
{
    __shared__ __align__(16) float sh_w[PAD_NODES * FANIN];   // ~32.9 KB

    const int tid = threadIdx.x;

    // Fold source responses into consumer weights:
    //   w'[i][t] = w[i][t] * resp[i + t - 16]  (identity for input sources).
    // Window carries RAW tanh values (packed pairs); resp applied at stores.
    for (int i = tid; i < N_NODES * FANIN; i += THREADS) {
        const int node = i >> 4, t = i & 15;
        const int g = node + t;
        const float s = (g >= N_IN) ? resp[g - N_IN] : 1.0f;
        sh_w[i] = w[i] * s;
    }
    for (int i = tid; i < 2 * FANIN; i += THREADS)
        sh_w[N_NODES * FANIN + i] = 0.0f;                      // pad rows
    __syncthreads();

    // One packed pair per thread: batch elements (b0, b0 + HALF).
    const int b0 = blockIdx.x * THREADS + tid;
    const int b1 = b0 + HALF;

    // Packed circular window: v2[g & 15] = {val_b0, val_b1} at global index g.
    u64 v2[16];
    {
        const float4* x0 = (const float4*)(x + (size_t)b0 * N_IN);
        const float4* x1 = (const float4*)(x + (size_t)b1 * N_IN);
        #pragma unroll
        for (int q = 0; q < 4; q++) {
            float4 t0 = x0[q], t1 = x1[q];
            v2[4*q+0] = pack2(t0.x, t1.x);
            v2[4*q+1] = pack2(t0.y, t1.y);
            v2[4*q+2] = pack2(t0.z, t1.z);
            v2[4*q+3] = pack2(t0.w, t1.w);
        }
    }

    float* outp0 = out + (size_t)b0 * N_OUT;
    float* outp1 = out + (size_t)b1 * N_OUT;
    const u32 wbase = smem_u32(sh_w);           // row stride 64 B

    // ---- Pipeline state ----
    // pp2    : packed partial of node n (taps 0..14 + bias)
    // w15c2  : packed w'[n][15]
    // wq[16] : packed weight row of node n+1 (duplicated LAST iteration)
    // pb2    : packed bias of node n+1
    u64 pp2, w15c2, wq[16], pb2;
    {
        const float* r0 = sh_w;                 // row 0 (scalar, one-time)
        u64 a0 = fma2(v2[0], dup2v(r0[0]), dup2v(cB[0]));
        u64 a1 = mul2(v2[1], dup2v(r0[1]));
        #pragma unroll
        for (int t = 2; t < 14; t += 2) {
            a0 = fma2(v2[t],     dup2v(r0[t]),     a0);
            a1 = fma2(v2[t + 1], dup2v(r0[t + 1]), a1);
        }
        a0 = fma2(v2[14], dup2v(r0[14]), a0);
        pp2 = add2(a0, a1);
        w15c2 = dup2v(r0[15]);

        const float* r1 = sh_w + FANIN;         // row 1 -> packed wq
        #pragma unroll
        for (int t = 0; t < 16; t++) wq[t] = dup2v(r1[t]);
        pb2 = dup2v(cB[1]);
    }

    float4 obA, obB;                            // output staging

    #pragma unroll 1
    for (int g = 0; g < N_NODES / 16; g++) {
        #pragma unroll
        for (int j = 0; j < 16; j++) {
            const int node = g * 16 + j;

            // ---- A: serial path (packed fma -> 2x tanh -> pack) ----
            const u64 yl2  = v2[(j + 15) & 15];         // y_{node-1} pair
            const u64 agg2 = fma2(yl2, w15c2, pp2);
            float aA, aB;
            unpack2(agg2, aA, aB);
            const float yA = tanh_approx(aA);
            const float yB = tanh_approx(aB);
            v2[j] = pack2(yA, yB);

            if (node >= OUT_START) {
                const int o = node - OUT_START;
                const float r = cR[o];
                const float oA = yA * r, oB = yB * r;
                if ((j & 3) == 0) { obA.x = oA; obB.x = oB; }
                if ((j & 3) == 1) { obA.y = oA; obB.y = oB; }
                if ((j & 3) == 2) { obA.z = oA; obB.z = oB; }
                if ((j & 3) == 3) {
                    obA.w = oA; obB.w = oB;
                    *(float4*)(outp0 + (o - 3)) = obA;
                    *(float4*)(outp1 + (o - 3)) = obB;
                }
            }

            // ---- B: prefetch weight row node+2 (volatile LDS) ----
            float4 nq0, nq1, nq2, nq3;
            const u32 ra = wbase + (u32)(node + 2) * 64;
            lds_v4(nq0, ra);
            lds_v4(nq1, ra + 16);
            lds_v4(nq2, ra + 32);
            lds_v4(nq3, ra + 48);

            // ---- C: packed 15-tap partial for node+1 from PRE-PACKED wq ----
            // All operands are >= 1 iteration old: no mov->fma exposure.
            u64 a0 = fma2(v2[(j + 1)  & 15], wq[0], pb2);
            u64 a1 = mul2(v2[(j + 2)  & 15], wq[1]);
            u64 a2 = mul2(v2[(j + 3)  & 15], wq[2]);
            u64 a3 = mul2(v2[(j + 4)  & 15], wq[3]);
            a0 = fma2(v2[(j + 5)  & 15], wq[4],  a0);
            a1 = fma2(v2[(j + 6)  & 15], wq[5],  a1);
            a2 = fma2(v2[(j + 7)  & 15], wq[6],  a2);
            a3 = fma2(v2[(j + 8)  & 15], wq[7],  a3);
            a0 = fma2(v2[(j + 9)  & 15], wq[8],  a0);
            a1 = fma2(v2[(j + 10) & 15], wq[9],  a1);
            a2 = fma2(v2[(j + 11) & 15], wq[10], a2);
            a3 = fma2(v2[(j + 12) & 15], wq[11], a3);
            a0 = fma2(v2[(j + 13) & 15], wq[12], a0);
            a1 = fma2(v2[(j + 14) & 15], wq[13], a1);
            a2 = fma2(v2[(j + 15) & 15], wq[14], a2);    // tap14 (newest) late
            pp2   = add2(add2(a0, a1), add2(a2, a3));
            w15c2 = wq[15];

            // ---- D: duplicate the just-loaded row for NEXT iteration ----
            // nq arrived ~40 instructions ago -> no LDS stall; volatile movs
            // stay here, so C never waits on a fresh ALU mov.
            wq[0]  = dup2v(nq0.x);  wq[1]  = dup2v(nq0.y);
            wq[2]  = dup2v(nq0.z);  wq[3]  = dup2v(nq0.w);
            wq[4]  = dup2v(nq1.x);  wq[5]  = dup2v(nq1.y);
            wq[6]  = dup2v(nq1.z);  wq[7]  = dup2v(nq1.w);
            wq[8]  = dup2v(nq2.x);  wq[9]  = dup2v(nq2.y);
            wq[10] = dup2v(nq2.z);  wq[11] = dup2v(nq2.w);
            wq[12] = dup2v(nq3.x);  wq[13] = dup2v(nq3.y);
            wq[14] = dup2v(nq3.z);  wq[15] = dup2v(nq3.w);
            pb2    = dup2v(cB[node + 2]);
        }
    }
}

extern "C" void kernel_launch(void* const* d_in, const int* in_sizes, int n_in,
                              void* d_out, int out_size) {
    const float* x    = (const float*)d_in[0];   // [BATCH, 16]
    const float* w    = (const float*)d_in[1];   // [512, 16]
    const float* bias = (const float*)d_in[2];   // [512]
    const float* resp = (const float*)d_in[3];   // [512]
    // d_in[4] (src_idx) is the fixed sliding-window topology; baked into indexing.
    float* out = (float*)d_out;                  // [BATCH, 64]

    cudaMemcpyToSymbolAsync(cB, bias, N_NODES * sizeof(float), 0,
                            cudaMemcpyDeviceToDevice, 0);
    cudaMemcpyToSymbolAsync(cR, resp + OUT_START, N_OUT * sizeof(float), 0,
                            cudaMemcpyDeviceToDevice, 0);

    neat_forward_rp3<<<GRID, THREADS>>>(x, w, resp, out);
}